// round 8
// baseline (speedup 1.0000x reference)
#include <cuda_runtime.h>
#include <cuda_bf16.h>
#include <cstdint>

#define B_SZ   128
#define NNODES 2047
#define LEAVES 1024
#define DIN    512
#define NL     64
#define MROWS  (B_SZ * NNODES)          // 262016

typedef unsigned long long u64;

// ---------------- device scratch (static; no allocations) ----------------
__device__ float g_emis[(size_t)B_SZ * NNODES * NL];   // 67 MB
__device__ float g_bufA[(size_t)B_SZ * 512 * NL];      // odd levels
__device__ float g_bufB[(size_t)B_SZ * 256 * NL];      // even levels
__device__ u64   g_w2[32 * NL];                        // [kp][l] packed exp(trans)
__device__ uint2 g_Wfrag2[32 * 8 * 32];                // [kstep][ntile][lane] {b0,b1} bf16x2

// ---------------- packed helpers ----------------
__device__ __forceinline__ u64 fma2(u64 a, u64 b, u64 c) {
    u64 d; asm("fma.rn.f32x2 %0, %1, %2, %3;" : "=l"(d) : "l"(a), "l"(b), "l"(c)); return d;
}
__device__ __forceinline__ u64 pack2(float lo, float hi) {
    u64 d; asm("mov.b64 %0, {%1, %2};" : "=l"(d) : "f"(lo), "f"(hi)); return d;
}
__device__ __forceinline__ float2 unpack2(u64 v) {
    float2 r; asm("mov.b64 {%0, %1}, %2;" : "=f"(r.x), "=f"(r.y) : "l"(v)); return r;
}
// single-rounded bf16x2 pack: low half = x0 (even k), high half = x1 (odd k)
__device__ __forceinline__ uint32_t cvt_bf2(float x0, float x1) {
    uint32_t h;
    asm("cvt.rn.satfinite.bf16x2.f32 %0, %1, %2;" : "=r"(h) : "f"(x1), "f"(x0));
    return h;
}
__device__ __forceinline__ void mma16816(float& d0, float& d1, float& d2, float& d3,
                                         uint32_t a0, uint32_t a1, uint32_t a2, uint32_t a3,
                                         uint32_t b0, uint32_t b1) {
    asm("mma.sync.aligned.m16n8k16.row.col.f32.bf16.bf16.f32 "
        "{%0,%1,%2,%3}, {%4,%5,%6,%7}, {%8,%9}, {%0,%1,%2,%3};"
        : "+f"(d0), "+f"(d1), "+f"(d2), "+f"(d3)
        : "r"(a0), "r"(a1), "r"(a2), "r"(a3), "r"(b0), "r"(b1));
}
__device__ __forceinline__ uint32_t smem_u32(const void* p) {
    uint32_t a; asm("{ .reg .u64 t; cvta.to.shared.u64 t, %1; cvt.u32.u64 %0, t; }" : "=r"(a) : "l"(p)); return a;
}
__device__ __forceinline__ void cp_async16(uint32_t dst, const void* src) {
    asm volatile("cp.async.cg.shared.global [%0], [%1], 16;" :: "r"(dst), "l"(src));
}

// ---------------- init: exp(trans) pairs + W b-fragments (bf16) ----------------
__global__ void init_kernel(const float* __restrict__ trans, const float* __restrict__ W) {
    int i = blockIdx.x * blockDim.x + threadIdx.x;
    if (i < 2048) {
        int kp = i >> 6, l = i & 63;
        float a = expf(trans[l * NL + 2 * kp]);
        float b = expf(trans[l * NL + 2 * kp + 1]);
        g_w2[kp * NL + l] = pack2(a, b);
    }
    int j = i - 2048;
    if (j >= 0 && j < 32 * 8 * 32) {
        int lane = j & 31, t = (j >> 5) & 7, s = j >> 8;
        int n  = t * 8 + (lane >> 2);
        int k0 = s * 16 + (lane & 3) * 2;
        uint32_t b0 = cvt_bf2(W[k0 * NL + n],       W[(k0 + 1) * NL + n]);
        uint32_t b1 = cvt_bf2(W[(k0 + 8) * NL + n], W[(k0 + 9) * NL + n]);
        g_Wfrag2[j] = make_uint2(b0, b1);
    }
}

// ---------------- HMMA emission GEMM: emis = hidden @ W + b ----------------
// CTA = 512 rows, 16 warps x 32 rows. cp.async 4-stage ring; single bf16 product.
// smem: Wfrag 64KB | 4 stages x 40KB (512 rows x 80B: 16 k-floats padded to 20) | bias
#define GS_W      0
#define GS_STAGE  65536
#define STAGE_BYTES 40960
#define GS_BIAS   (GS_STAGE + 4 * STAGE_BYTES)       // 229376
#define GS_TOTAL  (GS_BIAS + 256)                    // 229632

extern __shared__ char dynsm[];

__global__ __launch_bounds__(512) void gemm_kernel(
    const float* __restrict__ A, const float* __restrict__ bias,
    float* __restrict__ out)
{
    uint2* Wsm = (uint2*)dynsm;
    float* bsm = (float*)(dynsm + GS_BIAS);
    uint32_t sb = smem_u32(dynsm);
    int tid = threadIdx.x;
    {
        const uint4* src = (const uint4*)g_Wfrag2;
        uint4* dst = (uint4*)dynsm;
        for (int i = tid; i < 4096; i += 512) dst[i] = src[i];
        if (tid < NL) bsm[tid] = bias[tid];
    }

    long rowbase = (long)blockIdx.x * 512;
    int lane = tid & 31, w = tid >> 5;
    int qr = lane >> 2;            // 0..7
    int qk = lane & 3;             // quad k-pair selector

    // cp.async mapping: per stage, thread issues 4 x 16B; j = tid + 512*q
    // row = j>>2, chunk = j&3 (16B within the 64B k-slice)
    // --- prologue: stages 0..2 ---
#pragma unroll
    for (int st = 0; st < 3; ++st) {
#pragma unroll
        for (int q = 0; q < 4; ++q) {
            int j = tid + 512 * q;
            int row = j >> 2, ch = j & 3;
            long r = rowbase + row; if (r > MROWS - 1) r = MROWS - 1;
            const float* src = A + r * DIN + st * 16 + ch * 4;
            uint32_t dst = sb + GS_STAGE + st * STAGE_BYTES + row * 80 + ch * 16;
            cp_async16(dst, src);
        }
        asm volatile("cp.async.commit_group;" ::: "memory");
    }

    float acc[2][8][4];
#pragma unroll
    for (int rt = 0; rt < 2; ++rt)
#pragma unroll
        for (int t = 0; t < 8; ++t)
#pragma unroll
            for (int e = 0; e < 4; ++e) acc[rt][t][e] = 0.f;

    // thread's row offsets within the CTA tile (stage-local)
    int rloc0 = w * 32 + qr;       // rt0 row, rh0
    // syncthreads needed after W copy too; first loop-iteration barrier covers it? No:
    // warps may read Wsm before other warps wrote it. One explicit barrier here is safe
    // (cp.async groups unaffected by barrier).
    __syncthreads();

#pragma unroll 1
    for (int s = 0; s < 32; ++s) {
        asm volatile("cp.async.wait_group 2;" ::: "memory");
        __syncthreads();
        // issue stage s+3 into ring slot (s+3)&3
        if (s + 3 < 32) {
            int st = s + 3, slot = st & 3;
#pragma unroll
            for (int q = 0; q < 4; ++q) {
                int j = tid + 512 * q;
                int row = j >> 2, ch = j & 3;
                long r = rowbase + row; if (r > MROWS - 1) r = MROWS - 1;
                const float* src = A + r * DIN + st * 16 + ch * 4;
                uint32_t dst = sb + GS_STAGE + slot * STAGE_BYTES + row * 80 + ch * 16;
                cp_async16(dst, src);
            }
        }
        asm volatile("cp.async.commit_group;" ::: "memory");

        // compute on stage s
        const char* stg = dynsm + GS_STAGE + (s & 3) * STAGE_BYTES;
        uint32_t ah[2][4];
#pragma unroll
        for (int rt = 0; rt < 2; ++rt) {
            const char* base0 = stg + (rloc0 + rt * 16) * 80 + qk * 8;      // row +0
            const char* base8 = base0 + 8 * 80;                              // row +8
            float2 v00 = *(const float2*)(base0);        // k = qk*2, qk*2+1
            float2 v80 = *(const float2*)(base8);
            float2 v01 = *(const float2*)(base0 + 32);   // k = 8 + qk*2
            float2 v81 = *(const float2*)(base8 + 32);
            ah[rt][0] = cvt_bf2(v00.x, v00.y);
            ah[rt][1] = cvt_bf2(v80.x, v80.y);
            ah[rt][2] = cvt_bf2(v01.x, v01.y);
            ah[rt][3] = cvt_bf2(v81.x, v81.y);
        }
#pragma unroll
        for (int t = 0; t < 8; ++t) {
            uint2 wb = Wsm[(s * 8 + t) * 32 + lane];
#pragma unroll
            for (int rt = 0; rt < 2; ++rt) {
                mma16816(acc[rt][t][0], acc[rt][t][1], acc[rt][t][2], acc[rt][t][3],
                         ah[rt][0], ah[rt][1], ah[rt][2], ah[rt][3], wb.x, wb.y);
            }
        }
    }

    // epilogue: bias + store
    int qkc = qk * 2;
#pragma unroll
    for (int rt = 0; rt < 2; ++rt)
#pragma unroll
        for (int rh = 0; rh < 2; ++rh) {
            long r = rowbase + w * 32 + rt * 16 + rh * 8 + qr;
            if (r < MROWS) {
                float* orow = out + r * NL;
#pragma unroll
                for (int t = 0; t < 8; ++t) {
                    int c = t * 8 + qkc;
                    float2 v;
                    v.x = acc[rt][t][rh * 2 + 0] + bsm[c];
                    v.y = acc[rt][t][rh * 2 + 1] + bsm[c + 1];
                    *(float2*)(orow + c) = v;
                }
            }
        }
}

// ---------------- fused tree kernel (unchanged; near fma floor) ----------------
#define E2_PITCH 257
#define TREE_SMEM_BYTES ((2048 + 32 * E2_PITCH) * 8 + 256 * 4)

__global__ __launch_bounds__(512) void tree_kernel(
    const float* __restrict__ emis, float* __restrict__ bufA,
    float* __restrict__ bufB, float* __restrict__ outg)
{
    u64* smem = (u64*)dynsm;
    u64* W2s = smem;
    u64* E2s = smem + 2048;
    float* mbuf = (float*)(smem + 2048 + 32 * E2_PITCH);

    int t = threadIdx.x;
    int b = blockIdx.x;

    for (int i = t; i < 2048; i += 512) W2s[i] = g_w2[i];
    for (int i = t; i < 32 * E2_PITCH; i += 512) E2s[i] = 0ull;
    if (t < 256) mbuf[t] = 0.f;
    __syncthreads();

    const float* emisb = emis + (size_t)b * NNODES * NL;
    const float* prev  = emisb + (size_t)(LEAVES - 1) * NL;
    float* bufAb = bufA + (size_t)b * 512 * NL;
    float* bufBb = bufB + (size_t)b * 256 * NL;

    int cvg = t & 31, lg = t >> 5;
    int sub = t & 3,  cquad = t >> 2;

    for (int d = 9; d >= 0; --d) {
        int n = 1 << d;
        const float* emisLvl = emisb + (size_t)(n - 1) * NL;
        float* outLvl = (d == 0) ? (outg + (size_t)b * NL)
                                 : ((d & 1) ? bufAb : bufBb);
        int ntiles = (n + 127) >> 7;
        for (int tile = 0; tile < ntiles; ++tile) {
            int i0 = tile << 7;
            int NT = n - i0; if (NT > 128) NT = 128;
            int ncv = 2 * NT;

#pragma unroll
            for (int co = 0; co < 256; co += 128) {
                int c = co + cquad;
                bool valid = c < ncv;
                int cc = valid ? c : 0;
                const float* src = prev + (size_t)(i0 * 2 + cc) * NL + sub * 16;
                float4 v0 = *(const float4*)(src);
                float4 v1 = *(const float4*)(src + 4);
                float4 v2 = *(const float4*)(src + 8);
                float4 v3 = *(const float4*)(src + 12);
                float vv[16] = {v0.x, v0.y, v0.z, v0.w, v1.x, v1.y, v1.z, v1.w,
                                v2.x, v2.y, v2.z, v2.w, v3.x, v3.y, v3.z, v3.w};
                float m = vv[0];
#pragma unroll
                for (int j = 1; j < 16; ++j) m = fmaxf(m, vv[j]);
                m = fmaxf(m, __shfl_xor_sync(0xffffffffu, m, 1));
                m = fmaxf(m, __shfl_xor_sync(0xffffffffu, m, 2));
                if (valid) {
#pragma unroll
                    for (int j = 0; j < 8; ++j) {
                        float e0 = __expf(vv[2 * j] - m);
                        float e1 = __expf(vv[2 * j + 1] - m);
                        E2s[(sub * 8 + j) * E2_PITCH + c] = pack2(e0, e1);
                    }
                    if (sub == 0) mbuf[c] = m;
                }
            }
            __syncthreads();

            u64 acc[8][4];
#pragma unroll
            for (int i = 0; i < 8; ++i)
#pragma unroll
                for (int j = 0; j < 4; ++j) acc[i][j] = 0ull;

#pragma unroll 2
            for (int kp = 0; kp < 32; ++kp) {
                const u64* er = E2s + kp * E2_PITCH + cvg;
                const u64* wr = W2s + kp * NL + lg;
                u64 w0 = wr[0], w1 = wr[16], w2v = wr[32], w3 = wr[48];
#pragma unroll
                for (int i = 0; i < 8; ++i) {
                    u64 e = er[32 * i];
                    acc[i][0] = fma2(e, w0,  acc[i][0]);
                    acc[i][1] = fma2(e, w1,  acc[i][1]);
                    acc[i][2] = fma2(e, w2v, acc[i][2]);
                    acc[i][3] = fma2(e, w3,  acc[i][3]);
                }
            }

            bool isLeft = (cvg & 1) == 0;
#pragma unroll
            for (int i = 0; i < 8; ++i) {
                int cv = cvg + 32 * i;
                float mv = mbuf[cv];
#pragma unroll
                for (int j = 0; j < 4; ++j) {
                    float2 u = unpack2(acc[i][j]);
                    float lse = __logf(u.x + u.y) + mv;
                    float oth = __shfl_xor_sync(0xffffffffu, lse, 1);
                    if (isLeft && cv < ncv) {
                        int node = i0 + (cv >> 1);
                        int l = lg + 16 * j;
                        outLvl[(size_t)node * NL + l] =
                            emisLvl[(size_t)node * NL + l] + lse + oth;
                    }
                }
            }
            __syncthreads();
        }
        prev = outLvl;
    }
}

// ---------------- launch ----------------
extern "C" void kernel_launch(void* const* d_in, const int* in_sizes, int n_in,
                              void* d_out, int out_size)
{
    const float* hidden = (const float*)d_in[0];
    const float* W      = (const float*)d_in[1];
    const float* bias   = (const float*)d_in[2];
    const float* trans  = (const float*)d_in[3];
    float* out = (float*)d_out;

    float *emis, *bufA, *bufB;
    cudaGetSymbolAddress((void**)&emis, g_emis);
    cudaGetSymbolAddress((void**)&bufA, g_bufA);
    cudaGetSymbolAddress((void**)&bufB, g_bufB);

    init_kernel<<<(2048 + 32 * 8 * 32 + 255) / 256, 256>>>(trans, W);

    cudaFuncSetAttribute(gemm_kernel, cudaFuncAttributeMaxDynamicSharedMemorySize, GS_TOTAL);
    gemm_kernel<<<(MROWS + 511) / 512, 512, GS_TOTAL>>>(hidden, bias, emis);

    cudaFuncSetAttribute(tree_kernel, cudaFuncAttributeMaxDynamicSharedMemorySize, TREE_SMEM_BYTES);
    tree_kernel<<<B_SZ, 512, TREE_SMEM_BYTES>>>(emis, bufA, bufB, out);
}

// round 9
// speedup vs baseline: 1.5729x; 1.5729x over previous
#include <cuda_runtime.h>
#include <cuda_bf16.h>
#include <cstdint>

#define B_SZ   128
#define NNODES 2047
#define LEAVES 1024
#define DIN    512
#define NL     64
#define MROWS  (B_SZ * NNODES)          // 262016

typedef unsigned long long u64;

// ---------------- device scratch (static; no allocations) ----------------
__device__ float g_emis[(size_t)B_SZ * NNODES * NL];   // 67 MB
__device__ float g_bufA[(size_t)B_SZ * 512 * NL];      // odd levels
__device__ float g_bufB[(size_t)B_SZ * 256 * NL];      // even levels
__device__ u64   g_w2[32 * NL];                        // [kp][l] packed exp(trans)
__device__ uint4 g_Wfrag4[32 * 4 * 32];                // [kstep][tilepair][lane] {t0b0,t0b1,t1b0,t1b1}

// ---------------- packed helpers ----------------
__device__ __forceinline__ u64 fma2(u64 a, u64 b, u64 c) {
    u64 d; asm("fma.rn.f32x2 %0, %1, %2, %3;" : "=l"(d) : "l"(a), "l"(b), "l"(c)); return d;
}
__device__ __forceinline__ u64 pack2(float lo, float hi) {
    u64 d; asm("mov.b64 %0, {%1, %2};" : "=l"(d) : "f"(lo), "f"(hi)); return d;
}
__device__ __forceinline__ float2 unpack2(u64 v) {
    float2 r; asm("mov.b64 {%0, %1}, %2;" : "=f"(r.x), "=f"(r.y) : "l"(v)); return r;
}
// single-rounded bf16x2 pack: low half = x0 (even k), high half = x1 (odd k)
__device__ __forceinline__ uint32_t cvt_bf2(float x0, float x1) {
    uint32_t h;
    asm("cvt.rn.satfinite.bf16x2.f32 %0, %1, %2;" : "=r"(h) : "f"(x1), "f"(x0));
    return h;
}
__device__ __forceinline__ void mma16816(float& d0, float& d1, float& d2, float& d3,
                                         uint32_t a0, uint32_t a1, uint32_t a2, uint32_t a3,
                                         uint32_t b0, uint32_t b1) {
    asm("mma.sync.aligned.m16n8k16.row.col.f32.bf16.bf16.f32 "
        "{%0,%1,%2,%3}, {%4,%5,%6,%7}, {%8,%9}, {%0,%1,%2,%3};"
        : "+f"(d0), "+f"(d1), "+f"(d2), "+f"(d3)
        : "r"(a0), "r"(a1), "r"(a2), "r"(a3), "r"(b0), "r"(b1));
}

// ---------------- init: exp(trans) pairs + W b-fragments (tile-pair packed) ----------------
__global__ void init_kernel(const float* __restrict__ trans, const float* __restrict__ W) {
    int i = blockIdx.x * blockDim.x + threadIdx.x;
    if (i < 2048) {
        int kp = i >> 6, l = i & 63;
        float a = expf(trans[l * NL + 2 * kp]);
        float b = expf(trans[l * NL + 2 * kp + 1]);
        g_w2[kp * NL + l] = pack2(a, b);
    }
    int j = i - 2048;
    if (j >= 0 && j < 32 * 4 * 32) {
        int lane = j & 31, tp = (j >> 5) & 3, s = j >> 7;
        int k0 = s * 16 + (lane & 3) * 2;
        int n0 = (2 * tp) * 8 + (lane >> 2);
        int n1 = (2 * tp + 1) * 8 + (lane >> 2);
        uint32_t x0 = cvt_bf2(W[k0 * NL + n0],       W[(k0 + 1) * NL + n0]);
        uint32_t y0 = cvt_bf2(W[(k0 + 8) * NL + n0], W[(k0 + 9) * NL + n0]);
        uint32_t x1 = cvt_bf2(W[k0 * NL + n1],       W[(k0 + 1) * NL + n1]);
        uint32_t y1 = cvt_bf2(W[(k0 + 8) * NL + n1], W[(k0 + 9) * NL + n1]);
        g_Wfrag4[j] = make_uint4(x0, y0, x1, y1);
    }
}

// ---------------- HMMA emission GEMM: emis = hidden @ W + b ----------------
// CTA = 512 rows, 16 warps x 32 rows (2 m16 tiles). 2-product W-split bf16 MMA.
// Inner loop: convert(s) -> issue LDG(s+2) -> MMA(s): 2-deep in-flight window.
#define GS_TOTAL (65536 + 256)

extern __shared__ char dynsm[];

__global__ __launch_bounds__(512) void gemm_kernel(
    const float* __restrict__ A, const float* __restrict__ bias,
    float* __restrict__ out)
{
    uint4* Wsm = (uint4*)dynsm;
    float* bsm = (float*)(dynsm + 65536);
    int tid = threadIdx.x;
    {
        const uint4* src = g_Wfrag4;
        for (int i = tid; i < 4096; i += 512) Wsm[i] = src[i];
        if (tid < NL) bsm[tid] = bias[tid];
    }
    __syncthreads();

    int lane = tid & 31, w = tid >> 5;
    long rowbase = (long)blockIdx.x * 512 + w * 32;
    int qr = lane >> 2;            // 0..7
    int qk = lane & 3;             // 0..3

    const float* aptr[4];
#pragma unroll
    for (int rt = 0; rt < 2; ++rt)
#pragma unroll
        for (int rh = 0; rh < 2; ++rh) {
            long r = rowbase + rt * 16 + rh * 8 + qr;
            if (r > MROWS - 1) r = MROWS - 1;
            aptr[rt * 2 + rh] = A + r * DIN + qk * 2;
        }

    float acc[2][8][4];
#pragma unroll
    for (int rt = 0; rt < 2; ++rt)
#pragma unroll
        for (int t = 0; t < 8; ++t)
#pragma unroll
            for (int e = 0; e < 4; ++e) acc[rt][t][e] = 0.f;

    float2 buf[2][4][2];
#pragma unroll
    for (int p = 0; p < 4; ++p) {
        buf[0][p][0] = *(const float2*)(aptr[p]);
        buf[0][p][1] = *(const float2*)(aptr[p] + 8);
        buf[1][p][0] = *(const float2*)(aptr[p] + 16);
        buf[1][p][1] = *(const float2*)(aptr[p] + 24);
    }

#pragma unroll 1
    for (int s = 0; s < 32; ++s) {
        int pb = s & 1;
        // 1) convert fragments (frees buf[pb])
        uint32_t ah[2][4];
#pragma unroll
        for (int rt = 0; rt < 2; ++rt) {
            ah[rt][0] = cvt_bf2(buf[pb][2*rt][0].x,   buf[pb][2*rt][0].y);
            ah[rt][1] = cvt_bf2(buf[pb][2*rt+1][0].x, buf[pb][2*rt+1][0].y);
            ah[rt][2] = cvt_bf2(buf[pb][2*rt][1].x,   buf[pb][2*rt][1].y);
            ah[rt][3] = cvt_bf2(buf[pb][2*rt+1][1].x, buf[pb][2*rt+1][1].y);
        }
        // 2) issue loads for s+2 into the freed buffer
        if (s + 2 < 32) {
#pragma unroll
            for (int p = 0; p < 4; ++p) {
                buf[pb][p][0] = *(const float2*)(aptr[p] + (s + 2) * 16);
                buf[pb][p][1] = *(const float2*)(aptr[p] + (s + 2) * 16 + 8);
            }
        }
        // 3) MMAs (W tile-pairs via LDS.128)
#pragma unroll
        for (int tp = 0; tp < 4; ++tp) {
            uint4 wb = Wsm[(s * 4 + tp) * 32 + lane];
#pragma unroll
            for (int rt = 0; rt < 2; ++rt) {
                mma16816(acc[rt][2*tp][0],   acc[rt][2*tp][1],   acc[rt][2*tp][2],   acc[rt][2*tp][3],
                         ah[rt][0], ah[rt][1], ah[rt][2], ah[rt][3], wb.x, wb.y);
                mma16816(acc[rt][2*tp+1][0], acc[rt][2*tp+1][1], acc[rt][2*tp+1][2], acc[rt][2*tp+1][3],
                         ah[rt][0], ah[rt][1], ah[rt][2], ah[rt][3], wb.z, wb.w);
            }
        }
    }

    // epilogue: bias + store
    int qkc = qk * 2;
#pragma unroll
    for (int rt = 0; rt < 2; ++rt)
#pragma unroll
        for (int rh = 0; rh < 2; ++rh) {
            long r = rowbase + rt * 16 + rh * 8 + qr;
            if (r < MROWS) {
                float* orow = out + r * NL;
#pragma unroll
                for (int t = 0; t < 8; ++t) {
                    int c = t * 8 + qkc;
                    float2 v;
                    v.x = acc[rt][t][rh * 2 + 0] + bsm[c];
                    v.y = acc[rt][t][rh * 2 + 1] + bsm[c + 1];
                    *(float2*)(orow + c) = v;
                }
            }
        }
}

// ---------------- fused tree kernel ----------------
#define E2_PITCH 257
#define TREE_SMEM_BYTES ((2048 + 32 * E2_PITCH) * 8 + 256 * 4)

// phase 2 + epilogue, specialized on live cv-group count (NI = ceil(ncv/32))
template<int NI>
__device__ __forceinline__ void tree_phase2(
    const u64* __restrict__ E2s, const u64* __restrict__ W2s,
    const float* __restrict__ mbuf, const float* __restrict__ emisLvl,
    float* __restrict__ outLvl, int i0, int ncv, int cvg, int lg)
{
    u64 acc[NI][4];
#pragma unroll
    for (int i = 0; i < NI; ++i)
#pragma unroll
        for (int j = 0; j < 4; ++j) acc[i][j] = 0ull;

#pragma unroll 2
    for (int kp = 0; kp < 32; ++kp) {
        const u64* er = E2s + kp * E2_PITCH + cvg;
        const u64* wr = W2s + kp * NL + lg;
        u64 w0 = wr[0], w1 = wr[16], w2v = wr[32], w3 = wr[48];
#pragma unroll
        for (int i = 0; i < NI; ++i) {
            u64 e = er[32 * i];
            acc[i][0] = fma2(e, w0,  acc[i][0]);
            acc[i][1] = fma2(e, w1,  acc[i][1]);
            acc[i][2] = fma2(e, w2v, acc[i][2]);
            acc[i][3] = fma2(e, w3,  acc[i][3]);
        }
    }

    bool isLeft = (cvg & 1) == 0;
#pragma unroll
    for (int i = 0; i < NI; ++i) {
        int cv = cvg + 32 * i;
        float mv = mbuf[cv];
#pragma unroll
        for (int j = 0; j < 4; ++j) {
            float2 u = unpack2(acc[i][j]);
            float lse = __logf(u.x + u.y) + mv;
            float oth = __shfl_xor_sync(0xffffffffu, lse, 1);
            if (isLeft && cv < ncv) {
                int node = i0 + (cv >> 1);
                int l = lg + 16 * j;
                outLvl[(size_t)node * NL + l] =
                    emisLvl[(size_t)node * NL + l] + lse + oth;
            }
        }
    }
}

__global__ __launch_bounds__(512) void tree_kernel(
    const float* __restrict__ emis, float* __restrict__ bufA,
    float* __restrict__ bufB, float* __restrict__ outg)
{
    u64* smem = (u64*)dynsm;
    u64* W2s = smem;
    u64* E2s = smem + 2048;
    float* mbuf = (float*)(smem + 2048 + 32 * E2_PITCH);

    int t = threadIdx.x;
    int b = blockIdx.x;

    for (int i = t; i < 2048; i += 512) W2s[i] = g_w2[i];
    for (int i = t; i < 32 * E2_PITCH; i += 512) E2s[i] = 0ull;
    if (t < 256) mbuf[t] = 0.f;
    __syncthreads();

    const float* emisb = emis + (size_t)b * NNODES * NL;
    const float* prev  = emisb + (size_t)(LEAVES - 1) * NL;
    float* bufAb = bufA + (size_t)b * 512 * NL;
    float* bufBb = bufB + (size_t)b * 256 * NL;

    int cvg = t & 31, lg = t >> 5;
    int sub = t & 3,  cquad = t >> 2;

    for (int d = 9; d >= 0; --d) {
        int n = 1 << d;
        const float* emisLvl = emisb + (size_t)(n - 1) * NL;
        float* outLvl = (d == 0) ? (outg + (size_t)b * NL)
                                 : ((d & 1) ? bufAb : bufBb);
        int ntiles = (n + 127) >> 7;
        for (int tile = 0; tile < ntiles; ++tile) {
            int i0 = tile << 7;
            int NT = n - i0; if (NT > 128) NT = 128;
            int ncv = 2 * NT;

            // ---- phase 1: load children, per-cv max, exp, pack k-pairs ----
            auto phase1 = [&](int co) {
                int c = co + cquad;
                bool valid = c < ncv;
                int cc = valid ? c : 0;
                const float* src = prev + (size_t)(i0 * 2 + cc) * NL + sub * 16;
                float4 v0 = *(const float4*)(src);
                float4 v1 = *(const float4*)(src + 4);
                float4 v2 = *(const float4*)(src + 8);
                float4 v3 = *(const float4*)(src + 12);
                float vv[16] = {v0.x, v0.y, v0.z, v0.w, v1.x, v1.y, v1.z, v1.w,
                                v2.x, v2.y, v2.z, v2.w, v3.x, v3.y, v3.z, v3.w};
                float m = vv[0];
#pragma unroll
                for (int j = 1; j < 16; ++j) m = fmaxf(m, vv[j]);
                m = fmaxf(m, __shfl_xor_sync(0xffffffffu, m, 1));
                m = fmaxf(m, __shfl_xor_sync(0xffffffffu, m, 2));
                if (valid) {
#pragma unroll
                    for (int j = 0; j < 8; ++j) {
                        float e0 = __expf(vv[2 * j] - m);
                        float e1 = __expf(vv[2 * j + 1] - m);
                        E2s[(sub * 8 + j) * E2_PITCH + c] = pack2(e0, e1);
                    }
                    if (sub == 0) mbuf[c] = m;
                }
            };
            phase1(0);
            if (ncv > 128) phase1(128);
            __syncthreads();

            // ---- phase 2 (specialized on live width) ----
            if (ncv == 256)
                tree_phase2<8>(E2s, W2s, mbuf, emisLvl, outLvl, i0, ncv, cvg, lg);
            else if (ncv == 128)
                tree_phase2<4>(E2s, W2s, mbuf, emisLvl, outLvl, i0, ncv, cvg, lg);
            else if (ncv == 64)
                tree_phase2<2>(E2s, W2s, mbuf, emisLvl, outLvl, i0, ncv, cvg, lg);
            else
                tree_phase2<1>(E2s, W2s, mbuf, emisLvl, outLvl, i0, ncv, cvg, lg);
            __syncthreads();
        }
        prev = outLvl;
    }
}

// ---------------- launch ----------------
extern "C" void kernel_launch(void* const* d_in, const int* in_sizes, int n_in,
                              void* d_out, int out_size)
{
    const float* hidden = (const float*)d_in[0];
    const float* W      = (const float*)d_in[1];
    const float* bias   = (const float*)d_in[2];
    const float* trans  = (const float*)d_in[3];
    float* out = (float*)d_out;

    float *emis, *bufA, *bufB;
    cudaGetSymbolAddress((void**)&emis, g_emis);
    cudaGetSymbolAddress((void**)&bufA, g_bufA);
    cudaGetSymbolAddress((void**)&bufB, g_bufB);

    init_kernel<<<(2048 + 32 * 4 * 32 + 255) / 256, 256>>>(trans, W);

    cudaFuncSetAttribute(gemm_kernel, cudaFuncAttributeMaxDynamicSharedMemorySize, GS_TOTAL);
    gemm_kernel<<<(MROWS + 511) / 512, 512, GS_TOTAL>>>(hidden, bias, emis);

    cudaFuncSetAttribute(tree_kernel, cudaFuncAttributeMaxDynamicSharedMemorySize, TREE_SMEM_BYTES);
    tree_kernel<<<B_SZ, 512, TREE_SMEM_BYTES>>>(emis, bufA, bufB, out);
}

// round 11
// speedup vs baseline: 1.6622x; 1.0567x over previous
#include <cuda_runtime.h>
#include <cuda_bf16.h>
#include <cstdint>

#define B_SZ   128
#define NNODES 2047
#define LEAVES 1024
#define DIN    512
#define NL     64
#define MROWS  (B_SZ * NNODES)          // 262016

typedef unsigned long long u64;

// ---------------- device scratch (static; no allocations) ----------------
__device__ float g_emis[(size_t)B_SZ * NNODES * NL];   // 67 MB
__device__ float g_bufA[(size_t)B_SZ * 512 * NL];      // odd levels
__device__ float g_bufB[(size_t)B_SZ * 256 * NL];      // even levels
__device__ u64   g_w2[32 * NL];                        // [kp][l] packed exp(trans)
__device__ uint4 g_Wfrag4[32 * 4 * 32];                // [kstep][tilepair][lane], k-permuted

// ---------------- packed helpers ----------------
__device__ __forceinline__ u64 fma2(u64 a, u64 b, u64 c) {
    u64 d; asm("fma.rn.f32x2 %0, %1, %2, %3;" : "=l"(d) : "l"(a), "l"(b), "l"(c)); return d;
}
__device__ __forceinline__ u64 pack2(float lo, float hi) {
    u64 d; asm("mov.b64 %0, {%1, %2};" : "=l"(d) : "f"(lo), "f"(hi)); return d;
}
__device__ __forceinline__ float2 unpack2(u64 v) {
    float2 r; asm("mov.b64 {%0, %1}, %2;" : "=f"(r.x), "=f"(r.y) : "l"(v)); return r;
}
// single-rounded bf16x2 pack: low half = x0, high half = x1
__device__ __forceinline__ uint32_t cvt_bf2(float x0, float x1) {
    uint32_t h;
    asm("cvt.rn.satfinite.bf16x2.f32 %0, %1, %2;" : "=r"(h) : "f"(x1), "f"(x0));
    return h;
}
__device__ __forceinline__ void mma16816(float& d0, float& d1, float& d2, float& d3,
                                         uint32_t a0, uint32_t a1, uint32_t a2, uint32_t a3,
                                         uint32_t b0, uint32_t b1) {
    asm("mma.sync.aligned.m16n8k16.row.col.f32.bf16.bf16.f32 "
        "{%0,%1,%2,%3}, {%4,%5,%6,%7}, {%8,%9}, {%0,%1,%2,%3};"
        : "+f"(d0), "+f"(d1), "+f"(d2), "+f"(d3)
        : "r"(a0), "r"(a1), "r"(a2), "r"(a3), "r"(b0), "r"(b1));
}

// ---------------- init: exp(trans) pairs + k-permuted W b-fragments ----------------
// k-permutation: lane quad qk reads glob k = s*16 + 4qk .. 4qk+3, mapped to
// mma k-slots {2qk, 2qk+1} (reg b0/a0) and {2qk+8, 2qk+9} (reg b1/a2).
__global__ void init_kernel(const float* __restrict__ trans, const float* __restrict__ W) {
    int i = blockIdx.x * blockDim.x + threadIdx.x;
    if (i < 2048) {
        int kp = i >> 6, l = i & 63;
        float a = expf(trans[l * NL + 2 * kp]);
        float b = expf(trans[l * NL + 2 * kp + 1]);
        g_w2[kp * NL + l] = pack2(a, b);
    }
    int j = i - 2048;
    if (j >= 0 && j < 32 * 4 * 32) {
        int lane = j & 31, tp = (j >> 5) & 3, s = j >> 7;
        int k0 = s * 16 + (lane & 3) * 4;            // permuted: contiguous quad
        int n0 = (2 * tp) * 8 + (lane >> 2);
        int n1 = (2 * tp + 1) * 8 + (lane >> 2);
        uint32_t x0 = cvt_bf2(W[k0 * NL + n0],       W[(k0 + 1) * NL + n0]);  // b0 for n0
        uint32_t y0 = cvt_bf2(W[(k0 + 2) * NL + n0], W[(k0 + 3) * NL + n0]);  // b1 for n0
        uint32_t x1 = cvt_bf2(W[k0 * NL + n1],       W[(k0 + 1) * NL + n1]);
        uint32_t y1 = cvt_bf2(W[(k0 + 2) * NL + n1], W[(k0 + 3) * NL + n1]);
        g_Wfrag4[j] = make_uint4(x0, y0, x1, y1);
    }
}

// ---------------- HMMA emission GEMM: emis = hidden @ W + b ----------------
// CTA = 512 rows, 16 warps x 32 rows (2 m16 tiles). Single-product bf16 MMA.
// k-permuted A fragments: one LDG.128 per row-group per kstep (line-minimal).
#define GS_TOTAL (65536 + 256)

extern __shared__ char dynsm[];

__global__ __launch_bounds__(512) void gemm_kernel(
    const float* __restrict__ A, const float* __restrict__ bias,
    float* __restrict__ out)
{
    uint4* Wsm = (uint4*)dynsm;
    float* bsm = (float*)(dynsm + 65536);
    int tid = threadIdx.x;
    {
        const uint4* src = g_Wfrag4;
        for (int i = tid; i < 4096; i += 512) Wsm[i] = src[i];
        if (tid < NL) bsm[tid] = bias[tid];
    }
    __syncthreads();

    int lane = tid & 31, w = tid >> 5;
    long rowbase = (long)blockIdx.x * 512 + w * 32;
    int qr = lane >> 2;            // 0..7
    int qk = lane & 3;             // 0..3

    // 4 row pointers (float4-granular): p = rt*2 + rh -> row rt*16 + rh*8 + qr
    const float4* aptr[4];
#pragma unroll
    for (int rt = 0; rt < 2; ++rt)
#pragma unroll
        for (int rh = 0; rh < 2; ++rh) {
            long r = rowbase + rt * 16 + rh * 8 + qr;
            if (r > MROWS - 1) r = MROWS - 1;
            aptr[rt * 2 + rh] = (const float4*)(A + r * DIN) + qk;
        }

    float acc[2][8][4];
#pragma unroll
    for (int rt = 0; rt < 2; ++rt)
#pragma unroll
        for (int t = 0; t < 8; ++t)
#pragma unroll
            for (int e = 0; e < 4; ++e) acc[rt][t][e] = 0.f;

    // double buffer: one float4 per row pointer per kstep
    float4 buf[2][4];
#pragma unroll
    for (int p = 0; p < 4; ++p) {
        buf[0][p] = aptr[p][0];
        buf[1][p] = aptr[p][4];
    }

#pragma unroll 1
    for (int s = 0; s < 32; ++s) {
        int pb = s & 1;
        // 1) convert fragments (frees buf[pb]) — permuted slot mapping
        uint32_t ah[2][4];
#pragma unroll
        for (int rt = 0; rt < 2; ++rt) {
            float4 v0 = buf[pb][2 * rt];       // row qr   (+rt*16)
            float4 v1 = buf[pb][2 * rt + 1];   // row qr+8 (+rt*16)
            ah[rt][0] = cvt_bf2(v0.x, v0.y);   // a0: slots 2qk,2qk+1
            ah[rt][1] = cvt_bf2(v1.x, v1.y);   // a1
            ah[rt][2] = cvt_bf2(v0.z, v0.w);   // a2: slots 2qk+8,2qk+9
            ah[rt][3] = cvt_bf2(v1.z, v1.w);   // a3
        }
        // 2) issue loads for s+2 into the freed buffer
        if (s + 2 < 32) {
#pragma unroll
            for (int p = 0; p < 4; ++p) buf[pb][p] = aptr[p][(s + 2) * 4];
        }
        // 3) MMAs (W tile-pairs via LDS.128)
#pragma unroll
        for (int tp = 0; tp < 4; ++tp) {
            uint4 wb = Wsm[(s * 4 + tp) * 32 + lane];
#pragma unroll
            for (int rt = 0; rt < 2; ++rt) {
                mma16816(acc[rt][2*tp][0],   acc[rt][2*tp][1],   acc[rt][2*tp][2],   acc[rt][2*tp][3],
                         ah[rt][0], ah[rt][1], ah[rt][2], ah[rt][3], wb.x, wb.y);
                mma16816(acc[rt][2*tp+1][0], acc[rt][2*tp+1][1], acc[rt][2*tp+1][2], acc[rt][2*tp+1][3],
                         ah[rt][0], ah[rt][1], ah[rt][2], ah[rt][3], wb.z, wb.w);
            }
        }
    }

    // epilogue: bias + store
    int qkc = qk * 2;
#pragma unroll
    for (int rt = 0; rt < 2; ++rt)
#pragma unroll
        for (int rh = 0; rh < 2; ++rh) {
            long r = rowbase + rt * 16 + rh * 8 + qr;
            if (r < MROWS) {
                float* orow = out + r * NL;
#pragma unroll
                for (int t = 0; t < 8; ++t) {
                    int c = t * 8 + qkc;
                    float2 v;
                    v.x = acc[rt][t][rh * 2 + 0] + bsm[c];
                    v.y = acc[rt][t][rh * 2 + 1] + bsm[c + 1];
                    *(float2*)(orow + c) = v;
                }
            }
        }
}

// ---------------- fused tree kernel ----------------
#define E2_PITCH 257
#define TREE_SMEM_BYTES ((2048 + 32 * E2_PITCH) * 8 + 256 * 4)

template<int NI>
__device__ __forceinline__ void tree_phase2(
    const u64* __restrict__ E2s, const u64* __restrict__ W2s,
    const float* __restrict__ mbuf, const float* __restrict__ emisLvl,
    float* __restrict__ outLvl, int i0, int ncv, int cvg, int lg)
{
    u64 acc[NI][4];
#pragma unroll
    for (int i = 0; i < NI; ++i)
#pragma unroll
        for (int j = 0; j < 4; ++j) acc[i][j] = 0ull;

#pragma unroll 2
    for (int kp = 0; kp < 32; ++kp) {
        const u64* er = E2s + kp * E2_PITCH + cvg;
        const u64* wr = W2s + kp * NL + lg;
        u64 w0 = wr[0], w1 = wr[16], w2v = wr[32], w3 = wr[48];
#pragma unroll
        for (int i = 0; i < NI; ++i) {
            u64 e = er[32 * i];
            acc[i][0] = fma2(e, w0,  acc[i][0]);
            acc[i][1] = fma2(e, w1,  acc[i][1]);
            acc[i][2] = fma2(e, w2v, acc[i][2]);
            acc[i][3] = fma2(e, w3,  acc[i][3]);
        }
    }

    bool isLeft = (cvg & 1) == 0;
#pragma unroll
    for (int i = 0; i < NI; ++i) {
        int cv = cvg + 32 * i;
        float mv = mbuf[cv];
#pragma unroll
        for (int j = 0; j < 4; ++j) {
            float2 u = unpack2(acc[i][j]);
            float lse = __logf(u.x + u.y) + mv;
            float oth = __shfl_xor_sync(0xffffffffu, lse, 1);
            if (isLeft && cv < ncv) {
                int node = i0 + (cv >> 1);
                int l = lg + 16 * j;
                outLvl[(size_t)node * NL + l] =
                    emisLvl[(size_t)node * NL + l] + lse + oth;
            }
        }
    }
}

__global__ __launch_bounds__(512) void tree_kernel(
    const float* __restrict__ emis, float* __restrict__ bufA,
    float* __restrict__ bufB, float* __restrict__ outg)
{
    u64* smem = (u64*)dynsm;
    u64* W2s = smem;
    u64* E2s = smem + 2048;
    float* mbuf = (float*)(smem + 2048 + 32 * E2_PITCH);

    int t = threadIdx.x;
    int b = blockIdx.x;

    for (int i = t; i < 2048; i += 512) W2s[i] = g_w2[i];
    for (int i = t; i < 32 * E2_PITCH; i += 512) E2s[i] = 0ull;
    if (t < 256) mbuf[t] = 0.f;
    __syncthreads();

    const float* emisb = emis + (size_t)b * NNODES * NL;
    const float* prev  = emisb + (size_t)(LEAVES - 1) * NL;
    float* bufAb = bufA + (size_t)b * 512 * NL;
    float* bufBb = bufB + (size_t)b * 256 * NL;

    int cvg = t & 31, lg = t >> 5;
    int sub = t & 3,  cquad = t >> 2;

    for (int d = 9; d >= 0; --d) {
        int n = 1 << d;
        const float* emisLvl = emisb + (size_t)(n - 1) * NL;
        float* outLvl = (d == 0) ? (outg + (size_t)b * NL)
                                 : ((d & 1) ? bufAb : bufBb);
        int ntiles = (n + 127) >> 7;
        for (int tile = 0; tile < ntiles; ++tile) {
            int i0 = tile << 7;
            int NT = n - i0; if (NT > 128) NT = 128;
            int ncv = 2 * NT;

            auto phase1 = [&](int co) {
                int c = co + cquad;
                bool valid = c < ncv;
                int cc = valid ? c : 0;
                const float* src = prev + (size_t)(i0 * 2 + cc) * NL + sub * 16;
                float4 v0 = *(const float4*)(src);
                float4 v1 = *(const float4*)(src + 4);
                float4 v2 = *(const float4*)(src + 8);
                float4 v3 = *(const float4*)(src + 12);
                float vv[16] = {v0.x, v0.y, v0.z, v0.w, v1.x, v1.y, v1.z, v1.w,
                                v2.x, v2.y, v2.z, v2.w, v3.x, v3.y, v3.z, v3.w};
                float m = vv[0];
#pragma unroll
                for (int j = 1; j < 16; ++j) m = fmaxf(m, vv[j]);
                m = fmaxf(m, __shfl_xor_sync(0xffffffffu, m, 1));
                m = fmaxf(m, __shfl_xor_sync(0xffffffffu, m, 2));
                if (valid) {
#pragma unroll
                    for (int j = 0; j < 8; ++j) {
                        float e0 = __expf(vv[2 * j] - m);
                        float e1 = __expf(vv[2 * j + 1] - m);
                        E2s[(sub * 8 + j) * E2_PITCH + c] = pack2(e0, e1);
                    }
                    if (sub == 0) mbuf[c] = m;
                }
            };
            phase1(0);
            if (ncv > 128) phase1(128);
            __syncthreads();

            if (ncv == 256)
                tree_phase2<8>(E2s, W2s, mbuf, emisLvl, outLvl, i0, ncv, cvg, lg);
            else if (ncv == 128)
                tree_phase2<4>(E2s, W2s, mbuf, emisLvl, outLvl, i0, ncv, cvg, lg);
            else if (ncv == 64)
                tree_phase2<2>(E2s, W2s, mbuf, emisLvl, outLvl, i0, ncv, cvg, lg);
            else
                tree_phase2<1>(E2s, W2s, mbuf, emisLvl, outLvl, i0, ncv, cvg, lg);
            __syncthreads();
        }
        prev = outLvl;
    }
}

// ---------------- launch ----------------
extern "C" void kernel_launch(void* const* d_in, const int* in_sizes, int n_in,
                              void* d_out, int out_size)
{
    const float* hidden = (const float*)d_in[0];
    const float* W      = (const float*)d_in[1];
    const float* bias   = (const float*)d_in[2];
    const float* trans  = (const float*)d_in[3];
    float* out = (float*)d_out;

    float *emis, *bufA, *bufB;
    cudaGetSymbolAddress((void**)&emis, g_emis);
    cudaGetSymbolAddress((void**)&bufA, g_bufA);
    cudaGetSymbolAddress((void**)&bufB, g_bufB);

    // launched twice (idempotent): shifts the profiler's fixed launch-skip
    // so the captured launch is gemm_kernel, not init_kernel.
    init_kernel<<<(2048 + 32 * 4 * 32 + 255) / 256, 256>>>(trans, W);
    init_kernel<<<(2048 + 32 * 4 * 32 + 255) / 256, 256>>>(trans, W);

    cudaFuncSetAttribute(gemm_kernel, cudaFuncAttributeMaxDynamicSharedMemorySize, GS_TOTAL);
    gemm_kernel<<<(MROWS + 511) / 512, 512, GS_TOTAL>>>(hidden, bias, emis);

    cudaFuncSetAttribute(tree_kernel, cudaFuncAttributeMaxDynamicSharedMemorySize, TREE_SMEM_BYTES);
    tree_kernel<<<B_SZ, 512, TREE_SMEM_BYTES>>>(emis, bufA, bufB, out);
}

// round 12
// speedup vs baseline: 2.2877x; 1.3763x over previous
#include <cuda_runtime.h>
#include <cuda_bf16.h>
#include <cstdint>

#define B_SZ   128
#define NNODES 2047
#define LEAVES 1024
#define DIN    512
#define NL     64
#define MROWS  (B_SZ * NNODES)          // 262016

typedef unsigned long long u64;

// ---------------- device scratch (static; no allocations) ----------------
__device__ float g_emis[(size_t)B_SZ * NNODES * NL];   // 67 MB
__device__ float g_bufA[(size_t)B_SZ * 512 * NL];      // odd levels
__device__ float g_bufB[(size_t)B_SZ * 256 * NL];      // even levels
__device__ uint4 g_Wfrag4[32 * 4 * 32];                // GEMM W frags, k-permuted
__device__ uint4 g_Tfrag[4 * 8 * 32];                  // tree expT frags {xh,yh,xl,yl}

// ---------------- packed helpers ----------------
__device__ __forceinline__ uint32_t cvt_bf2(float x0, float x1) {
    uint32_t h;
    asm("cvt.rn.satfinite.bf16x2.f32 %0, %1, %2;" : "=r"(h) : "f"(x1), "f"(x0));
    return h;
}
__device__ __forceinline__ void cvt_hilo(float x0, float x1, uint32_t& h, uint32_t& l) {
    asm("cvt.rn.satfinite.bf16x2.f32 %0, %1, %2;" : "=r"(h) : "f"(x1), "f"(x0));
    float r0 = x0 - __uint_as_float(h << 16);
    float r1 = x1 - __uint_as_float(h & 0xffff0000u);
    asm("cvt.rn.satfinite.bf16x2.f32 %0, %1, %2;" : "=r"(l) : "f"(r1), "f"(r0));
}
__device__ __forceinline__ void mma16816(float& d0, float& d1, float& d2, float& d3,
                                         uint32_t a0, uint32_t a1, uint32_t a2, uint32_t a3,
                                         uint32_t b0, uint32_t b1) {
    asm("mma.sync.aligned.m16n8k16.row.col.f32.bf16.bf16.f32 "
        "{%0,%1,%2,%3}, {%4,%5,%6,%7}, {%8,%9}, {%0,%1,%2,%3};"
        : "+f"(d0), "+f"(d1), "+f"(d2), "+f"(d3)
        : "r"(a0), "r"(a1), "r"(a2), "r"(a3), "r"(b0), "r"(b1));
}

// ---------------- init: GEMM W frags + tree expT frags (hi/lo) ----------------
__global__ void init_kernel(const float* __restrict__ trans, const float* __restrict__ W) {
    int i = blockIdx.x * blockDim.x + threadIdx.x;
    if (i < 4 * 8 * 32) {
        int lane = i & 31, nt = (i >> 5) & 7, s = i >> 8;
        int n  = nt * 8 + (lane >> 2);
        int k0 = s * 16 + (lane & 3) * 4;
        float t0 = expf(trans[n * NL + k0]);
        float t1 = expf(trans[n * NL + k0 + 1]);
        float t2 = expf(trans[n * NL + k0 + 2]);
        float t3 = expf(trans[n * NL + k0 + 3]);
        uint32_t xh, xl, yh, yl;
        cvt_hilo(t0, t1, xh, xl);
        cvt_hilo(t2, t3, yh, yl);
        g_Tfrag[i] = make_uint4(xh, yh, xl, yl);
    }
    int j = i - 2048;
    if (j >= 0 && j < 32 * 4 * 32) {
        int lane = j & 31, tp = (j >> 5) & 3, s = j >> 7;
        int k0 = s * 16 + (lane & 3) * 4;            // permuted: contiguous quad
        int n0 = (2 * tp) * 8 + (lane >> 2);
        int n1 = (2 * tp + 1) * 8 + (lane >> 2);
        uint32_t x0 = cvt_bf2(W[k0 * NL + n0],       W[(k0 + 1) * NL + n0]);
        uint32_t y0 = cvt_bf2(W[(k0 + 2) * NL + n0], W[(k0 + 3) * NL + n0]);
        uint32_t x1 = cvt_bf2(W[k0 * NL + n1],       W[(k0 + 1) * NL + n1]);
        uint32_t y1 = cvt_bf2(W[(k0 + 2) * NL + n1], W[(k0 + 3) * NL + n1]);
        g_Wfrag4[j] = make_uint4(x0, y0, x1, y1);
    }
}

// ---------------- HMMA emission GEMM (unchanged from R11 best) ----------------
#define GS_TOTAL (65536 + 256)

extern __shared__ char dynsm[];

__global__ __launch_bounds__(512) void gemm_kernel(
    const float* __restrict__ A, const float* __restrict__ bias,
    float* __restrict__ out)
{
    uint4* Wsm = (uint4*)dynsm;
    float* bsm = (float*)(dynsm + 65536);
    int tid = threadIdx.x;
    {
        const uint4* src = g_Wfrag4;
        for (int i = tid; i < 4096; i += 512) Wsm[i] = src[i];
        if (tid < NL) bsm[tid] = bias[tid];
    }
    __syncthreads();

    int lane = tid & 31, w = tid >> 5;
    long rowbase = (long)blockIdx.x * 512 + w * 32;
    int qr = lane >> 2;
    int qk = lane & 3;

    const float4* aptr[4];
#pragma unroll
    for (int rt = 0; rt < 2; ++rt)
#pragma unroll
        for (int rh = 0; rh < 2; ++rh) {
            long r = rowbase + rt * 16 + rh * 8 + qr;
            if (r > MROWS - 1) r = MROWS - 1;
            aptr[rt * 2 + rh] = (const float4*)(A + r * DIN) + qk;
        }

    float acc[2][8][4];
#pragma unroll
    for (int rt = 0; rt < 2; ++rt)
#pragma unroll
        for (int t = 0; t < 8; ++t)
#pragma unroll
            for (int e = 0; e < 4; ++e) acc[rt][t][e] = 0.f;

    float4 buf[2][4];
#pragma unroll
    for (int p = 0; p < 4; ++p) {
        buf[0][p] = aptr[p][0];
        buf[1][p] = aptr[p][4];
    }

#pragma unroll 1
    for (int s = 0; s < 32; ++s) {
        int pb = s & 1;
        uint32_t ah[2][4];
#pragma unroll
        for (int rt = 0; rt < 2; ++rt) {
            float4 v0 = buf[pb][2 * rt];
            float4 v1 = buf[pb][2 * rt + 1];
            ah[rt][0] = cvt_bf2(v0.x, v0.y);
            ah[rt][1] = cvt_bf2(v1.x, v1.y);
            ah[rt][2] = cvt_bf2(v0.z, v0.w);
            ah[rt][3] = cvt_bf2(v1.z, v1.w);
        }
        if (s + 2 < 32) {
#pragma unroll
            for (int p = 0; p < 4; ++p) buf[pb][p] = aptr[p][(s + 2) * 4];
        }
#pragma unroll
        for (int tp = 0; tp < 4; ++tp) {
            uint4 wb = Wsm[(s * 4 + tp) * 32 + lane];
#pragma unroll
            for (int rt = 0; rt < 2; ++rt) {
                mma16816(acc[rt][2*tp][0],   acc[rt][2*tp][1],   acc[rt][2*tp][2],   acc[rt][2*tp][3],
                         ah[rt][0], ah[rt][1], ah[rt][2], ah[rt][3], wb.x, wb.y);
                mma16816(acc[rt][2*tp+1][0], acc[rt][2*tp+1][1], acc[rt][2*tp+1][2], acc[rt][2*tp+1][3],
                         ah[rt][0], ah[rt][1], ah[rt][2], ah[rt][3], wb.z, wb.w);
            }
        }
    }

    int qkc = qk * 2;
#pragma unroll
    for (int rt = 0; rt < 2; ++rt)
#pragma unroll
        for (int rh = 0; rh < 2; ++rh) {
            long r = rowbase + rt * 16 + rh * 8 + qr;
            if (r < MROWS) {
                float* orow = out + r * NL;
#pragma unroll
                for (int t = 0; t < 8; ++t) {
                    int c = t * 8 + qkc;
                    float2 v;
                    v.x = acc[rt][t][rh * 2 + 0] + bsm[c];
                    v.y = acc[rt][t][rh * 2 + 1] + bsm[c + 1];
                    *(float2*)(orow + c) = v;
                }
            }
        }
}

// ---------------- fused tree kernel v2: HMMA merge ----------------
// smem: Tfrag 16KB | E[256 cv][pitch 34 u64] (f32 pairs) 69632B | mbuf 1KB
#define EPITCH 34
#define TS_E    16384
#define TS_MBUF (TS_E + 256 * EPITCH * 8)            // 86016
#define TREE_SMEM_BYTES (TS_MBUF + 1024)             // 87040

__global__ __launch_bounds__(512) void tree_kernel(
    const float* __restrict__ emis, float* __restrict__ bufA,
    float* __restrict__ bufB, float* __restrict__ outg)
{
    uint4* Tsm = (uint4*)dynsm;
    float* Ebase = (float*)(dynsm + TS_E);           // viewed as f32; pitch 68 floats
    float* mbuf = (float*)(dynsm + TS_MBUF);

    int t = threadIdx.x;
    int b = blockIdx.x;

    for (int i = t; i < 1024; i += 512) Tsm[i] = g_Tfrag[i];
    __syncthreads();

    const float* emisb = emis + (size_t)b * NNODES * NL;
    const float* prev  = emisb + (size_t)(LEAVES - 1) * NL;
    float* bufAb = bufA + (size_t)b * 512 * NL;
    float* bufBb = bufB + (size_t)b * 256 * NL;

    int lane = t & 31, w = t >> 5;
    int qr = lane >> 2, qk = lane & 3;
    int m0 = w * 16;                     // warp's cv-row base
    bool gEven = (qr & 1) == 0;
    int sub = t & 3, cquad = t >> 2;

    for (int d = 9; d >= 0; --d) {
        int n = 1 << d;
        const float* emisLvl = emisb + (size_t)(n - 1) * NL;
        float* outLvl = (d == 0) ? (outg + (size_t)b * NL)
                                 : ((d & 1) ? bufAb : bufBb);
        int ntiles = (n + 127) >> 7;
        for (int tile = 0; tile < ntiles; ++tile) {
            int i0 = tile << 7;
            int NT = n - i0; if (NT > 128) NT = 128;
            int ncv = 2 * NT;

            // ---- phase 1: load children, per-cv max, exp, store f32 to E ----
            auto phase1 = [&](int co) {
                int c = co + cquad;
                bool valid = c < ncv;
                int cc = valid ? c : 0;
                const float* src = prev + (size_t)(i0 * 2 + cc) * NL + sub * 16;
                float4 v0 = *(const float4*)(src);
                float4 v1 = *(const float4*)(src + 4);
                float4 v2 = *(const float4*)(src + 8);
                float4 v3 = *(const float4*)(src + 12);
                float vv[16] = {v0.x, v0.y, v0.z, v0.w, v1.x, v1.y, v1.z, v1.w,
                                v2.x, v2.y, v2.z, v2.w, v3.x, v3.y, v3.z, v3.w};
                float m = vv[0];
#pragma unroll
                for (int j = 1; j < 16; ++j) m = fmaxf(m, vv[j]);
                m = fmaxf(m, __shfl_xor_sync(0xffffffffu, m, 1));
                m = fmaxf(m, __shfl_xor_sync(0xffffffffu, m, 2));
                if (valid) {
                    float* erow = Ebase + c * (EPITCH * 2) + sub * 16;
#pragma unroll
                    for (int j = 0; j < 4; ++j) {
                        float4 ev;
                        ev.x = __expf(vv[4 * j]     - m);
                        ev.y = __expf(vv[4 * j + 1] - m);
                        ev.z = __expf(vv[4 * j + 2] - m);
                        ev.w = __expf(vv[4 * j + 3] - m);
                        *(float4*)(erow + 4 * j) = ev;
                    }
                    if (sub == 0) mbuf[c] = m;
                }
            };
            phase1(0);
            if (ncv > 128) phase1(128);
            __syncthreads();

            // ---- phase 2: warp-level HMMA merge (warp owns 16 cv rows) ----
            if (m0 < ncv) {
                float acc[8][4];
#pragma unroll
                for (int nt = 0; nt < 8; ++nt)
#pragma unroll
                    for (int e = 0; e < 4; ++e) acc[nt][e] = 0.f;

#pragma unroll
                for (int s = 0; s < 4; ++s) {
                    const float* ep = Ebase + (m0 + qr) * (EPITCH * 2) + s * 16 + qk * 4;
                    float4 va = *(const float4*)(ep);
                    float4 vb = *(const float4*)(ep + 8 * EPITCH * 2);
                    uint32_t a0 = cvt_bf2(va.x, va.y);
                    uint32_t a1 = cvt_bf2(vb.x, vb.y);
                    uint32_t a2 = cvt_bf2(va.z, va.w);
                    uint32_t a3 = cvt_bf2(vb.z, vb.w);
#pragma unroll
                    for (int nt = 0; nt < 8; ++nt) {
                        uint4 wf = Tsm[(s * 8 + nt) * 32 + lane];
                        mma16816(acc[nt][0], acc[nt][1], acc[nt][2], acc[nt][3],
                                 a0, a1, a2, a3, wf.x, wf.y);   // hi
                        mma16816(acc[nt][0], acc[nt][1], acc[nt][2], acc[nt][3],
                                 a0, a1, a2, a3, wf.z, wf.w);   // lo
                    }
                }

                // ---- epilogue: log + m, combine L/R via shfl_xor(4), store ----
                int cvA = m0 + qr, cvB = m0 + qr + 8;
                float mA = mbuf[cvA], mB = mbuf[cvB];
                int nodeA = i0 + (cvA >> 1), nodeB = i0 + (cvB >> 1);
                int col = qk * 2;
#pragma unroll
                for (int nt = 0; nt < 8; ++nt) {
                    float l0 = __logf(acc[nt][0]) + mA;
                    float l1 = __logf(acc[nt][1]) + mA;
                    float l2 = __logf(acc[nt][2]) + mB;
                    float l3 = __logf(acc[nt][3]) + mB;
                    float o0 = __shfl_xor_sync(0xffffffffu, l0, 4);
                    float o1 = __shfl_xor_sync(0xffffffffu, l1, 4);
                    float o2 = __shfl_xor_sync(0xffffffffu, l2, 4);
                    float o3 = __shfl_xor_sync(0xffffffffu, l3, 4);
                    if (gEven) {
                        int c0 = nt * 8 + col;
                        if (cvA < ncv) {
                            float2 em = *(const float2*)(emisLvl + (size_t)nodeA * NL + c0);
                            float2 v; v.x = em.x + l0 + o0; v.y = em.y + l1 + o1;
                            *(float2*)(outLvl + (size_t)nodeA * NL + c0) = v;
                        }
                        if (cvB < ncv) {
                            float2 em = *(const float2*)(emisLvl + (size_t)nodeB * NL + c0);
                            float2 v; v.x = em.x + l2 + o2; v.y = em.y + l3 + o3;
                            *(float2*)(outLvl + (size_t)nodeB * NL + c0) = v;
                        }
                    }
                }
            }
            __syncthreads();
        }
        prev = outLvl;
    }
}

// ---------------- launch ----------------
extern "C" void kernel_launch(void* const* d_in, const int* in_sizes, int n_in,
                              void* d_out, int out_size)
{
    const float* hidden = (const float*)d_in[0];
    const float* W      = (const float*)d_in[1];
    const float* bias   = (const float*)d_in[2];
    const float* trans  = (const float*)d_in[3];
    float* out = (float*)d_out;

    float *emis, *bufA, *bufB;
    cudaGetSymbolAddress((void**)&emis, g_emis);
    cudaGetSymbolAddress((void**)&bufA, g_bufA);
    cudaGetSymbolAddress((void**)&bufB, g_bufB);

    init_kernel<<<(2048 + 32 * 4 * 32 + 255) / 256, 256>>>(trans, W);
    init_kernel<<<(2048 + 32 * 4 * 32 + 255) / 256, 256>>>(trans, W);

    cudaFuncSetAttribute(gemm_kernel, cudaFuncAttributeMaxDynamicSharedMemorySize, GS_TOTAL);
    gemm_kernel<<<(MROWS + 511) / 512, 512, GS_TOTAL>>>(hidden, bias, emis);

    cudaFuncSetAttribute(tree_kernel, cudaFuncAttributeMaxDynamicSharedMemorySize, TREE_SMEM_BYTES);
    tree_kernel<<<B_SZ, 512, TREE_SMEM_BYTES>>>(emis, bufA, bufB, out);
}